// round 1
// baseline (speedup 1.0000x reference)
#include <cuda_runtime.h>

// Normalized correlation layer, GB300 sm_103a.
// out[b,r,j,c, d*12+j2] = corr over 5x5 patch (per channel c) of
//   normalized patch1(b, r, j) vs normalized patch2(b, row2[r+d], j2)
// Using identity: sum((a-ma)(b-mb))/(sa*sb) = (S_ab - 25*ma*mb) * (1/sa) * (1/sb)
// Pass 1 computes per-patch per-channel mean & rstd for both images.
// Pass 2 correlates RAW padded values with f32x2 packed FMAs and applies the
// correction at the epilogue.

#define NB  16
#define NR  37
#define NC  12
#define NCH 128
#define NCP 64       // channel pairs (f32x2)
#define OUTLAST 7680 // 128 * 60

typedef unsigned long long u64;

__device__ __forceinline__ u64 fma2_(u64 a, u64 b, u64 c) {
    u64 d; asm("fma.rn.f32x2 %0, %1, %2, %3;" : "=l"(d) : "l"(a), "l"(b), "l"(c)); return d;
}
__device__ __forceinline__ u64 mul2_(u64 a, u64 b) {
    u64 d; asm("mul.rn.f32x2 %0, %1, %2;" : "=l"(d) : "l"(a), "l"(b)); return d;
}
__device__ __forceinline__ u64 add2_(u64 a, u64 b) {
    u64 d; asm("add.rn.f32x2 %0, %1, %2;" : "=l"(d) : "l"(a), "l"(b)); return d;
}
__device__ __forceinline__ u64 pk2(float x, float y) {
    u64 r; asm("mov.b64 %0, {%1, %2};" : "=l"(r) : "f"(x), "f"(y)); return r;
}
__device__ __forceinline__ float2 upk2(u64 v) {
    float2 f; asm("mov.b64 {%0, %1}, %2;" : "=f"(f.x), "=f"(f.y) : "l"(v)); return f;
}

// Stats scratch (static device globals — no runtime allocation).
// Image1: row starts 0..36.  Image2: row starts 0..38 (39 values).
__device__ float g_mA[NB * NR * NC * NCH];
__device__ float g_rA[NB * NR * NC * NCH];
__device__ float g_mB[NB * 39 * NC * NCH];
__device__ float g_rB[NB * 39 * NC * NCH];

// ---------------------------------------------------------------------------
// Pass 1: per-patch per-channel mean and rstd.
// grid.x: 0..36 -> image1 row start r; 37..75 -> image2 row start (x-37).
// grid.y: batch.
// ---------------------------------------------------------------------------
__global__ __launch_bounds__(384) void nc_stats_kernel(
    const float* __restrict__ in1, const float* __restrict__ in2)
{
    __shared__ u64 slab[5 * 16 * 64];  // 40 KB: 5 padded rows x 16 padded cols x 64 ch-pairs
    const int bx  = blockIdx.x;
    const int b   = blockIdx.y;
    const int tid = threadIdx.x;

    const bool img1 = bx < NR;
    const int  st   = img1 ? bx : bx - NR;          // patch row start in padded coords
    const int  roff = img1 ? 2 : 4;                 // padded row -> input row offset
    const u64* inv  = (const u64*)(img1 ? in1 : in2);

    for (int i = tid; i < 5 * 16 * 64; i += 384) {
        int c = i & 63, col = (i >> 6) & 15, dr = i >> 10;
        int row = st + dr - roff;
        int cg  = col - 2;
        u64 v = 0ull;
        if ((unsigned)row < 37u && (unsigned)cg < 12u)
            v = inv[((b * 37 + row) * 12 + cg) * 64 + c];
        slab[i] = v;
    }
    __syncthreads();

    float2* gm = (float2*)(img1 ? g_mA : g_mB);
    float2* gr = (float2*)(img1 ? g_rA : g_rB);
    const int nrows = img1 ? NR : 39;

    for (int t = tid; t < 12 * 64; t += 384) {
        int j = t >> 6, c = t & 63;
        u64 s = 0ull, q = 0ull;
        #pragma unroll
        for (int dr = 0; dr < 5; dr++) {
            #pragma unroll
            for (int dc = 0; dc < 5; dc++) {
                u64 v = slab[(dr * 16 + j + dc) * 64 + c];
                s = add2_(s, v);
                q = fma2_(v, v, q);
            }
        }
        float2 sf = upk2(s), qf = upk2(q);
        float mx = sf.x * 0.04f, my = sf.y * 0.04f;
        float vx = qf.x * 0.04f - mx * mx;
        float vy = qf.y * 0.04f - my * my;
        int idx = ((b * nrows + st) * 12 + j) * 64 + c;
        gm[idx] = make_float2(mx, my);
        gr[idx] = make_float2(rsqrtf(vx), rsqrtf(vy));
    }
}

// ---------------------------------------------------------------------------
// Pass 2: correlation. One CTA per (r, b). 384 threads = 64 ch-pairs x 6 j-pairs.
// ---------------------------------------------------------------------------
#define SM_S1 0
#define SM_S2 (5 * 16 * 64)                // 5120
#define SM_MA (SM_S2 + 9 * 16 * 64)        // +9216
#define SM_RA (SM_MA + 12 * 64)
#define SM_MB (SM_RA + 12 * 64)
#define SM_RB (SM_MB + 5 * 12 * 64)
#define SM_TOT (SM_RB + 5 * 12 * 64)       // 23552 u64 = 188416 B

__global__ __launch_bounds__(384, 1) void nc_corr_kernel(
    const float* __restrict__ in1, const float* __restrict__ in2,
    float* __restrict__ out)
{
    extern __shared__ u64 sm[];
    const int r   = blockIdx.x;
    const int b   = blockIdx.y;
    const int tid = threadIdx.x;

    const u64* in1v = (const u64*)in1;
    const u64* in2v = (const u64*)in2;

    // Slab of padded image1: pad1 rows r..r+4 (input rows r-2..r+2), cols 0..15.
    for (int i = tid; i < 5 * 16 * 64; i += 384) {
        int c = i & 63, col = (i >> 6) & 15, dr = i >> 10;
        int row = r + dr - 2, cg = col - 2;
        u64 v = 0ull;
        if ((unsigned)row < 37u && (unsigned)cg < 12u)
            v = in1v[((b * 37 + row) * 12 + cg) * 64 + c];
        sm[SM_S1 + i] = v;
    }
    // Slab of padded image2: pad2 rows r..r+8 (input rows r-4..r+4).
    for (int i = tid; i < 9 * 16 * 64; i += 384) {
        int c = i & 63, col = (i >> 6) & 15, dr = i >> 10;
        int row = r + dr - 4, cg = col - 2;
        u64 v = 0ull;
        if ((unsigned)row < 37u && (unsigned)cg < 12u)
            v = in2v[((b * 37 + row) * 12 + cg) * 64 + c];
        sm[SM_S2 + i] = v;
    }
    // Stats for image1 patches at this r.
    const u64* mAv = (const u64*)g_mA;
    const u64* rAv = (const u64*)g_rA;
    const u64* mBv = (const u64*)g_mB;
    const u64* rBv = (const u64*)g_rB;
    for (int i = tid; i < 12 * 64; i += 384) {
        int j = i >> 6, c = i & 63;
        int gi = ((b * 37 + r) * 12 + j) * 64 + c;
        sm[SM_MA + i] = mAv[gi];
        sm[SM_RA + i] = rAv[gi];
    }
    // Stats for image2 patches with row starts r+s, s in 0..4 (clamped to 38).
    for (int i = tid; i < 5 * 12 * 64; i += 384) {
        int c = i & 63, j = (i >> 6) % 12, s = i / 768;
        int stv = r + s; if (stv > 38) stv = 38;
        int gi = ((b * 39 + stv) * 12 + j) * 64 + c;
        sm[SM_MB + i] = mBv[gi];
        sm[SM_RB + i] = rBv[gi];
    }
    __syncthreads();

    const int cp = tid & 63;       // channel pair: channels 2cp, 2cp+1
    const int jp = tid >> 6;       // 0..5
    const int j0 = jp << 1;        // handles j0, j0+1

    const u64 ma0 = sm[SM_MA + (j0 << 6) + cp];
    const u64 ma1 = sm[SM_MA + ((j0 + 1) << 6) + cp];
    const u64 ra0 = sm[SM_RA + (j0 << 6) + cp];
    const u64 ra1 = sm[SM_RA + ((j0 + 1) << 6) + cp];
    const u64 neg25 = pk2(-25.0f, -25.0f);
    const u64 na0 = mul2_(ma0, neg25);
    const u64 na1 = mul2_(ma1, neg25);

    const int obase = ((b * 37 + r) * 12 + j0) * OUTLAST + (cp << 1) * 60;

    #pragma unroll 1
    for (int d = 0; d < 5; d++) {
        // row2[i] = i for i<=38, else i-2 (duplicated tail rows).
        const int sd = (r + d <= 38) ? d : d - 2;

        u64 acc0[12], acc1[12];
        #pragma unroll
        for (int t = 0; t < 12; t++) { acc0[t] = 0ull; acc1[t] = 0ull; }

        #pragma unroll 1
        for (int dr = 0; dr < 5; dr++) {
            const u64* rowB = sm + SM_S2 + ((sd + dr) << 10) + cp;
            const u64* rowA = sm + SM_S1 + (dr << 10) + (j0 << 6) + cp;
            u64 a2[16];
            #pragma unroll
            for (int x = 0; x < 16; x++) a2[x] = rowB[x << 6];
            u64 a1[6];
            #pragma unroll
            for (int x = 0; x < 6; x++) a1[x] = rowA[x << 6];
            #pragma unroll
            for (int dc = 0; dc < 5; dc++) {
                #pragma unroll
                for (int j2 = 0; j2 < 12; j2++) {
                    acc0[j2] = fma2_(a1[dc],     a2[j2 + dc], acc0[j2]);
                    acc1[j2] = fma2_(a1[dc + 1], a2[j2 + dc], acc1[j2]);
                }
            }
        }

        // Epilogue: apply (S - 25*ma*mb) * ra * rb, unpack, vector stores.
        float o00[12], o01[12], o10[12], o11[12];
        #pragma unroll
        for (int j2 = 0; j2 < 12; j2++) {
            u64 mb = sm[SM_MB + ((sd * 12 + j2) << 6) + cp];
            u64 rb = sm[SM_RB + ((sd * 12 + j2) << 6) + cp];
            u64 rr0 = mul2_(ra0, rb);
            u64 rr1 = mul2_(ra1, rb);
            float2 v0 = upk2(mul2_(fma2_(na0, mb, acc0[j2]), rr0));
            float2 v1 = upk2(mul2_(fma2_(na1, mb, acc1[j2]), rr1));
            o00[j2] = v0.x; o01[j2] = v0.y;
            o10[j2] = v1.x; o11[j2] = v1.y;
        }
        float* p = out + obase + d * 12;
        #pragma unroll
        for (int q = 0; q < 3; q++) {
            ((float4*)(p))[q]                 = ((float4*)o00)[q];
            ((float4*)(p + 60))[q]            = ((float4*)o01)[q];
            ((float4*)(p + OUTLAST))[q]       = ((float4*)o10)[q];
            ((float4*)(p + OUTLAST + 60))[q]  = ((float4*)o11)[q];
        }
    }
}

// ---------------------------------------------------------------------------
extern "C" void kernel_launch(void* const* d_in, const int* in_sizes, int n_in,
                              void* d_out, int out_size)
{
    const float* in1 = (const float*)d_in[0];
    const float* in2 = (const float*)d_in[1];
    float* out = (float*)d_out;

    cudaFuncSetAttribute(nc_corr_kernel,
                         cudaFuncAttributeMaxDynamicSharedMemorySize,
                         SM_TOT * (int)sizeof(u64));

    nc_stats_kernel<<<dim3(NR + 39, NB), 384>>>(in1, in2);
    nc_corr_kernel<<<dim3(NR, NB), 384, SM_TOT * sizeof(u64)>>>(in1, in2, out);
}